// round 1
// baseline (speedup 1.0000x reference)
#include <cuda_runtime.h>

namespace {
constexpr int B  = 8;
constexpr int S  = 1024;
constexpr int H  = 1024;
constexpr int NH = 16;
constexpr int HD = 64;
constexpr int M  = B * S;    // 8192 rows
constexpr int BH = B * NH;   // 128 heads
constexpr float SCALE  = 0.125f;   // 1/sqrt(64)
constexpr float LN_EPS = 1e-12f;
}

// Scratch (allocation-free: __device__ globals)
__device__ float g_q[BH * S * HD];          // 32 MB
__device__ float g_k[BH * S * HD];          // 32 MB
__device__ float g_v[BH * S * HD];          // 32 MB
__device__ float g_scores[BH * S * S];      // 512 MB
__device__ float g_ctx[M * H];              // 32 MB
__device__ float g_proj[M * H];             // 32 MB

// ---------------------------------------------------------------------------
// GEMM: C[M,1024] = X[M,1024] @ W[1024,1024]^T + bias   (NT, K=1024)
// dst_sel: 0/1/2 -> q/k/v head-split layout, 3 -> g_proj plain (X := g_ctx)
// ---------------------------------------------------------------------------
__global__ __launch_bounds__(256, 1)
void gemm_xw(const float* __restrict__ Xin,
             const float* __restrict__ W,
             const float* __restrict__ bias,
             int dst_sel)
{
    const float* X = Xin ? Xin : g_ctx;
    float* dst = (dst_sel == 0) ? g_q : (dst_sel == 1) ? g_k
               : (dst_sel == 2) ? g_v : g_proj;
    const bool headsplit = dst_sel < 3;

    __shared__ float As[16][128];
    __shared__ float Bs[16][128];

    const int tid = threadIdx.x;
    const int bm  = blockIdx.y * 128;
    const int bn  = blockIdx.x * 128;
    const int tx  = tid & 15;
    const int ty  = tid >> 4;
    const int r0  = tid >> 2;
    const int c0  = (tid & 3) * 4;

    float acc[8][8];
#pragma unroll
    for (int i = 0; i < 8; i++)
#pragma unroll
        for (int j = 0; j < 8; j++) acc[i][j] = 0.f;

    for (int k0 = 0; k0 < H; k0 += 16) {
#pragma unroll
        for (int l = 0; l < 2; l++) {
            const int r = r0 + l * 64;
            float4 va = *(const float4*)&X[(size_t)(bm + r) * H + k0 + c0];
            As[c0+0][r] = va.x; As[c0+1][r] = va.y;
            As[c0+2][r] = va.z; As[c0+3][r] = va.w;
            float4 vb = *(const float4*)&W[(size_t)(bn + r) * H + k0 + c0];
            Bs[c0+0][r] = vb.x; Bs[c0+1][r] = vb.y;
            Bs[c0+2][r] = vb.z; Bs[c0+3][r] = vb.w;
        }
        __syncthreads();
#pragma unroll
        for (int k = 0; k < 16; k++) {
            float a[8], b[8];
            *(float4*)&a[0] = *(const float4*)&As[k][ty*8];
            *(float4*)&a[4] = *(const float4*)&As[k][ty*8+4];
            *(float4*)&b[0] = *(const float4*)&Bs[k][tx*8];
            *(float4*)&b[4] = *(const float4*)&Bs[k][tx*8+4];
#pragma unroll
            for (int i = 0; i < 8; i++)
#pragma unroll
                for (int j = 0; j < 8; j++)
                    acc[i][j] = fmaf(a[i], b[j], acc[i][j]);
        }
        __syncthreads();
    }

#pragma unroll
    for (int i = 0; i < 8; i++) {
        const int row = bm + ty*8 + i;
        const int b_  = row >> 10;
        const int s_  = row & 1023;
#pragma unroll
        for (int j = 0; j < 8; j++) {
            const int col = bn + tx*8 + j;
            const float v = acc[i][j] + bias[col];
            if (headsplit) {
                const int h_ = col >> 6;
                const int d_ = col & 63;
                dst[((size_t)(b_*NH + h_) * S + s_) * HD + d_] = v;
            } else {
                dst[(size_t)row * H + col] = v;
            }
        }
    }
}

// ---------------------------------------------------------------------------
// Scores: Sc[q,k] = (Q[q,:] . K[k,:]) * SCALE + mask[b,k]   per head (K=64)
// ---------------------------------------------------------------------------
__global__ __launch_bounds__(256, 1)
void attn_scores(const float* __restrict__ mask)
{
    const int head = blockIdx.z;
    const int b_   = head >> 4;
    const float* Q = g_q + (size_t)head * S * HD;
    const float* K = g_k + (size_t)head * S * HD;
    float* Sc      = g_scores + (size_t)head * S * S;

    __shared__ float As[16][128];
    __shared__ float Bs[16][128];

    const int tid = threadIdx.x;
    const int bm  = blockIdx.y * 128;
    const int bn  = blockIdx.x * 128;
    const int tx  = tid & 15;
    const int ty  = tid >> 4;
    const int r0  = tid >> 2;
    const int c0  = (tid & 3) * 4;

    float acc[8][8];
#pragma unroll
    for (int i = 0; i < 8; i++)
#pragma unroll
        for (int j = 0; j < 8; j++) acc[i][j] = 0.f;

    for (int k0 = 0; k0 < HD; k0 += 16) {
#pragma unroll
        for (int l = 0; l < 2; l++) {
            const int r = r0 + l * 64;
            float4 va = *(const float4*)&Q[(size_t)(bm + r) * HD + k0 + c0];
            As[c0+0][r] = va.x; As[c0+1][r] = va.y;
            As[c0+2][r] = va.z; As[c0+3][r] = va.w;
            float4 vb = *(const float4*)&K[(size_t)(bn + r) * HD + k0 + c0];
            Bs[c0+0][r] = vb.x; Bs[c0+1][r] = vb.y;
            Bs[c0+2][r] = vb.z; Bs[c0+3][r] = vb.w;
        }
        __syncthreads();
#pragma unroll
        for (int k = 0; k < 16; k++) {
            float a[8], b[8];
            *(float4*)&a[0] = *(const float4*)&As[k][ty*8];
            *(float4*)&a[4] = *(const float4*)&As[k][ty*8+4];
            *(float4*)&b[0] = *(const float4*)&Bs[k][tx*8];
            *(float4*)&b[4] = *(const float4*)&Bs[k][tx*8+4];
#pragma unroll
            for (int i = 0; i < 8; i++)
#pragma unroll
                for (int j = 0; j < 8; j++)
                    acc[i][j] = fmaf(a[i], b[j], acc[i][j]);
        }
        __syncthreads();
    }

#pragma unroll
    for (int i = 0; i < 8; i++) {
        const int q = bm + ty*8 + i;
#pragma unroll
        for (int j = 0; j < 8; j++) {
            const int kk = bn + tx*8 + j;
            Sc[(size_t)q * S + kk] = acc[i][j] * SCALE + mask[b_ * S + kk];
        }
    }
}

// ---------------------------------------------------------------------------
// Row softmax over g_scores, in place. One block per row (256 thr x 4 elems).
// ---------------------------------------------------------------------------
__global__ __launch_bounds__(256, 1)
void softmax_rows()
{
    float* row = g_scores + (size_t)blockIdx.x * S;
    const int tid = threadIdx.x;
    __shared__ float red[8];

    float4 v = *(const float4*)&row[tid * 4];
    float m = fmaxf(fmaxf(v.x, v.y), fmaxf(v.z, v.w));
#pragma unroll
    for (int o = 16; o; o >>= 1) m = fmaxf(m, __shfl_xor_sync(~0u, m, o));
    if ((tid & 31) == 0) red[tid >> 5] = m;
    __syncthreads();
    float mm = -3.4e38f;
#pragma unroll
    for (int i = 0; i < 8; i++) mm = fmaxf(mm, red[i]);

    v.x = __expf(v.x - mm); v.y = __expf(v.y - mm);
    v.z = __expf(v.z - mm); v.w = __expf(v.w - mm);
    float s = v.x + v.y + v.z + v.w;
#pragma unroll
    for (int o = 16; o; o >>= 1) s += __shfl_xor_sync(~0u, s, o);
    __syncthreads();
    if ((tid & 31) == 0) red[tid >> 5] = s;
    __syncthreads();
    float tot = 0.f;
#pragma unroll
    for (int i = 0; i < 8; i++) tot += red[i];

    const float inv = 1.f / tot;
    v.x *= inv; v.y *= inv; v.z *= inv; v.w *= inv;
    *(float4*)&row[tid * 4] = v;
}

// ---------------------------------------------------------------------------
// ctx = P @ V per head (NN, M=1024,N=64,K=1024); writes [B,S,H] layout.
// ---------------------------------------------------------------------------
__global__ __launch_bounds__(256, 1)
void attn_ctx()
{
    const int head = blockIdx.z;
    const int b_   = head >> 4;
    const int h_   = head & 15;
    const float* P = g_scores + (size_t)head * S * S;
    const float* V = g_v + (size_t)head * S * HD;

    __shared__ float As[16][128];
    __shared__ float Bs[16][64];

    const int tid = threadIdx.x;
    const int bm  = blockIdx.y * 128;
    const int tx  = tid & 15;   // 4 cols each -> 64
    const int ty  = tid >> 4;   // 8 rows each -> 128
    const int r0  = tid >> 2;
    const int c0  = (tid & 3) * 4;
    const int kr  = tid >> 4;        // B-load row 0..15
    const int cc  = (tid & 15) * 4;  // B-load col

    float acc[8][4];
#pragma unroll
    for (int i = 0; i < 8; i++)
#pragma unroll
        for (int j = 0; j < 4; j++) acc[i][j] = 0.f;

    for (int k0 = 0; k0 < S; k0 += 16) {
#pragma unroll
        for (int l = 0; l < 2; l++) {
            const int r = r0 + l * 64;
            float4 va = *(const float4*)&P[(size_t)(bm + r) * S + k0 + c0];
            As[c0+0][r] = va.x; As[c0+1][r] = va.y;
            As[c0+2][r] = va.z; As[c0+3][r] = va.w;
        }
        float4 vb = *(const float4*)&V[(size_t)(k0 + kr) * HD + cc];
        *(float4*)&Bs[kr][cc] = vb;
        __syncthreads();
#pragma unroll
        for (int k = 0; k < 16; k++) {
            float a[8], b[4];
            *(float4*)&a[0] = *(const float4*)&As[k][ty*8];
            *(float4*)&a[4] = *(const float4*)&As[k][ty*8+4];
            *(float4*)&b[0] = *(const float4*)&Bs[k][tx*4];
#pragma unroll
            for (int i = 0; i < 8; i++)
#pragma unroll
                for (int j = 0; j < 4; j++)
                    acc[i][j] = fmaf(a[i], b[j], acc[i][j]);
        }
        __syncthreads();
    }

#pragma unroll
    for (int i = 0; i < 8; i++) {
        const int q = bm + ty*8 + i;
#pragma unroll
        for (int j = 0; j < 4; j++) {
            const int d = tx*4 + j;
            g_ctx[((size_t)(b_ * S + q)) * H + h_ * HD + d] = acc[i][j];
        }
    }
}

// ---------------------------------------------------------------------------
// out = LayerNorm(g_proj + hidden) * gamma + beta   (one block per row)
// ---------------------------------------------------------------------------
__global__ __launch_bounds__(256, 1)
void add_ln(const float* __restrict__ hidden,
            const float* __restrict__ gamma,
            const float* __restrict__ beta,
            float* __restrict__ out)
{
    const size_t row = blockIdx.x;
    const int tid = threadIdx.x;
    __shared__ float r1[8], r2[8];

    float4 a  = *(const float4*)&g_proj[row * H + tid * 4];
    float4 hv = *(const float4*)&hidden[row * H + tid * 4];
    float x0 = a.x + hv.x, x1 = a.y + hv.y, x2 = a.z + hv.z, x3 = a.w + hv.w;

    float s1 = x0 + x1 + x2 + x3;
    float s2 = fmaf(x0, x0, fmaf(x1, x1, fmaf(x2, x2, x3 * x3)));
#pragma unroll
    for (int o = 16; o; o >>= 1) {
        s1 += __shfl_xor_sync(~0u, s1, o);
        s2 += __shfl_xor_sync(~0u, s2, o);
    }
    if ((tid & 31) == 0) { r1[tid >> 5] = s1; r2[tid >> 5] = s2; }
    __syncthreads();
    float t1 = 0.f, t2 = 0.f;
#pragma unroll
    for (int i = 0; i < 8; i++) { t1 += r1[i]; t2 += r2[i]; }

    const float mu  = t1 * (1.f / H);
    const float var = t2 * (1.f / H) - mu * mu;
    const float inv = rsqrtf(var + LN_EPS);

    float4 g  = *(const float4*)&gamma[tid * 4];
    float4 bt = *(const float4*)&beta[tid * 4];
    float4 o;
    o.x = (x0 - mu) * inv * g.x + bt.x;
    o.y = (x1 - mu) * inv * g.y + bt.y;
    o.z = (x2 - mu) * inv * g.z + bt.z;
    o.w = (x3 - mu) * inv * g.w + bt.w;
    *(float4*)&out[row * H + tid * 4] = o;
}

// ---------------------------------------------------------------------------
extern "C" void kernel_launch(void* const* d_in, const int* in_sizes, int n_in,
                              void* d_out, int out_size)
{
    const float* hidden = (const float*)d_in[0];
    const float* mask   = (const float*)d_in[1];
    const float* Wq     = (const float*)d_in[2];
    const float* bq     = (const float*)d_in[3];
    const float* Wk     = (const float*)d_in[4];
    const float* bk     = (const float*)d_in[5];
    const float* Wv     = (const float*)d_in[6];
    const float* bv     = (const float*)d_in[7];
    const float* Wo     = (const float*)d_in[8];
    const float* bo     = (const float*)d_in[9];
    const float* gamma  = (const float*)d_in[10];
    const float* beta   = (const float*)d_in[11];
    float* out          = (float*)d_out;

    dim3 blk(256);
    dim3 gqkv(H / 128, M / 128);        // (8, 64)
    gemm_xw<<<gqkv, blk>>>(hidden, Wq, bq, 0);
    gemm_xw<<<gqkv, blk>>>(hidden, Wk, bk, 1);
    gemm_xw<<<gqkv, blk>>>(hidden, Wv, bv, 2);

    dim3 gsc(S / 128, S / 128, BH);     // (8, 8, 128)
    attn_scores<<<gsc, blk>>>(mask);

    softmax_rows<<<BH * S, blk>>>();

    dim3 gctx(1, S / 128, BH);          // (1, 8, 128)
    attn_ctx<<<gctx, blk>>>();

    gemm_xw<<<gqkv, blk>>>(nullptr, Wo, bo, 3);

    add_ln<<<M, blk>>>(hidden, gamma, beta, out);
}

// round 3
// speedup vs baseline: 2.4128x; 2.4128x over previous
#include <cuda_runtime.h>
#include <cuda_bf16.h>
#include <cstdint>

namespace {
constexpr int B  = 8;
constexpr int S  = 1024;
constexpr int H  = 1024;
constexpr int NH = 16;
constexpr int HD = 64;
constexpr int M  = B * S;    // 8192 rows
constexpr int BH = B * NH;   // 128 heads
constexpr float SCALE  = 0.125f;
constexpr float LN_EPS = 1e-12f;
constexpr int BK = 32;       // K-slab per stage
}

// ---------------------------------------------------------------------------
// Scratch (allocation-free: __device__ globals)
// ---------------------------------------------------------------------------
__device__ float g_q[BH * S * HD];
__device__ float g_k[BH * S * HD];
__device__ float g_v[BH * S * HD];
__device__ float g_scores[BH * S * S];
__device__ float g_ctx[M * H];
__device__ float g_proj[M * H];

// ---------------------------------------------------------------------------
// Warp-MMA helpers (sm_80+ feature set: valid on plain sm_103 target)
// ---------------------------------------------------------------------------
__device__ __forceinline__ uint32_t smem_u32(const void* p) {
    uint32_t a;
    asm("{ .reg .u64 t; cvta.to.shared.u64 t, %1; cvt.u32.u64 %0, t; }"
        : "=r"(a) : "l"(p));
    return a;
}
__device__ __forceinline__ void mma_bf16(float* c, const uint32_t* a, const uint32_t* b) {
    asm volatile(
        "mma.sync.aligned.m16n8k16.row.col.f32.bf16.bf16.f32 "
        "{%0,%1,%2,%3}, {%4,%5,%6,%7}, {%8,%9}, {%0,%1,%2,%3};"
        : "+f"(c[0]), "+f"(c[1]), "+f"(c[2]), "+f"(c[3])
        : "r"(a[0]), "r"(a[1]), "r"(a[2]), "r"(a[3]), "r"(b[0]), "r"(b[1]));
}
__device__ __forceinline__ void ldm_x4(uint32_t* r, uint32_t addr) {
    asm volatile("ldmatrix.sync.aligned.m8n8.x4.shared.b16 {%0,%1,%2,%3}, [%4];"
                 : "=r"(r[0]), "=r"(r[1]), "=r"(r[2]), "=r"(r[3]) : "r"(addr));
}
__device__ __forceinline__ void ldm_x2(uint32_t* r, uint32_t addr) {
    asm volatile("ldmatrix.sync.aligned.m8n8.x2.shared.b16 {%0,%1}, [%2];"
                 : "=r"(r[0]), "=r"(r[1]) : "r"(addr));
}
__device__ __forceinline__ void ldm_x2t(uint32_t* r, uint32_t addr) {
    asm volatile("ldmatrix.sync.aligned.m8n8.x2.trans.shared.b16 {%0,%1}, [%2];"
                 : "=r"(r[0]), "=r"(r[1]) : "r"(addr));
}
// Split (x,y) into packed bf16x2 hi and residual lo.
__device__ __forceinline__ void split2(float x, float y, uint32_t& hi, uint32_t& lo) {
    asm("cvt.rn.bf16x2.f32 %0, %1, %2;" : "=r"(hi) : "f"(y), "f"(x));
    float hx = __uint_as_float(hi << 16);
    float hy = __uint_as_float(hi & 0xFFFF0000u);
    float rx = x - hx;
    float ry = y - hy;
    asm("cvt.rn.bf16x2.f32 %0, %1, %2;" : "=r"(lo) : "f"(ry), "f"(rx));
}
__device__ __forceinline__ void sts_f4(uint16_t* hiA, uint16_t* loA, int idx, float4 f) {
    uint32_t h0, l0, h1, l1;
    split2(f.x, f.y, h0, l0);
    split2(f.z, f.w, h1, l1);
    *(uint32_t*)&hiA[idx]     = h0;
    *(uint32_t*)&hiA[idx + 2] = h1;
    *(uint32_t*)&loA[idx]     = l0;
    *(uint32_t*)&loA[idx + 2] = l1;
}

// ---------------------------------------------------------------------------
// Projection GEMM: C[M,1024] = X @ W^T + bias.  128x128 tile, 8 warps (64x32).
// bf16 hi/lo split: 3 MMAs per k-step tile pair.
// dst_sel: 0/1/2 -> q/k/v headsplit layout; 3 -> g_proj (X := g_ctx)
// ---------------------------------------------------------------------------
__global__ __launch_bounds__(256, 1)
void gemm_mma(const float* __restrict__ Xin,
              const float* __restrict__ W,
              const float* __restrict__ bias,
              int dst_sel)
{
    __shared__ __align__(16) uint16_t sAhi[128][40];
    __shared__ __align__(16) uint16_t sAlo[128][40];
    __shared__ __align__(16) uint16_t sBhi[128][40];
    __shared__ __align__(16) uint16_t sBlo[128][40];

    const float* X = Xin ? Xin : g_ctx;
    float* dst = (dst_sel == 0) ? g_q : (dst_sel == 1) ? g_k
               : (dst_sel == 2) ? g_v : g_proj;
    const bool headsplit = dst_sel < 3;

    const int tid  = threadIdx.x;
    const int lane = tid & 31;
    const int wid  = tid >> 5;
    const int bm   = blockIdx.y * 128;
    const int bn   = blockIdx.x * 128;
    const int m_off = (wid & 1) * 64;
    const int n_off = (wid >> 1) * 32;

    const int lr = tid >> 1;          // load row 0..127
    const int lk = (tid & 1) * 16;    // k half within slab
    const float* xrow = X + (size_t)(bm + lr) * H + lk;
    const float* wrow = W + (size_t)(bn + lr) * H + lk;

    float4 bufA[4], bufB[4];
#pragma unroll
    for (int q = 0; q < 4; q++) {
        bufA[q] = *(const float4*)(xrow + q * 4);
        bufB[q] = *(const float4*)(wrow + q * 4);
    }

    float acc[4][4][4];
#pragma unroll
    for (int i = 0; i < 4; i++)
#pragma unroll
        for (int j = 0; j < 4; j++)
#pragma unroll
            for (int t = 0; t < 4; t++) acc[i][j][t] = 0.f;

    const int NS = H / BK;  // 32 slabs
    for (int s = 0; s < NS; s++) {
#pragma unroll
        for (int q = 0; q < 4; q++) {
            sts_f4(&sAhi[lr][0], &sAlo[lr][0], lk + q * 4, bufA[q]);
            sts_f4(&sBhi[lr][0], &sBlo[lr][0], lk + q * 4, bufB[q]);
        }
        __syncthreads();
        if (s + 1 < NS) {
            const float* xp = xrow + (size_t)(s + 1) * BK;
            const float* wp = wrow + (size_t)(s + 1) * BK;
#pragma unroll
            for (int q = 0; q < 4; q++) {
                bufA[q] = *(const float4*)(xp + q * 4);
                bufB[q] = *(const float4*)(wp + q * 4);
            }
        }
#pragma unroll
        for (int kk = 0; kk < 2; kk++) {
            const int kel = kk * 16;
            uint32_t ah[4][4], al[4][4], bh[4][2], bl[4][2];
            const int ar = m_off + (lane & 15);
            const int ac = kel + (lane >> 4) * 8;
#pragma unroll
            for (int mi = 0; mi < 4; mi++) {
                ldm_x4(ah[mi], smem_u32(&sAhi[ar + mi * 16][ac]));
                ldm_x4(al[mi], smem_u32(&sAlo[ar + mi * 16][ac]));
            }
            const int br = n_off + (lane & 7);
            const int bc = kel + ((lane >> 3) & 1) * 8;
#pragma unroll
            for (int ni = 0; ni < 4; ni++) {
                ldm_x2(bh[ni], smem_u32(&sBhi[br + ni * 8][bc]));
                ldm_x2(bl[ni], smem_u32(&sBlo[br + ni * 8][bc]));
            }
#pragma unroll
            for (int mi = 0; mi < 4; mi++)
#pragma unroll
                for (int ni = 0; ni < 4; ni++) {
                    mma_bf16(acc[mi][ni], ah[mi], bh[ni]);
                    mma_bf16(acc[mi][ni], ah[mi], bl[ni]);
                    mma_bf16(acc[mi][ni], al[mi], bh[ni]);
                }
        }
        __syncthreads();
    }

    // Epilogue: direct float2 stores with bias
#pragma unroll
    for (int mi = 0; mi < 4; mi++) {
#pragma unroll
        for (int ni = 0; ni < 4; ni++) {
            const int col = bn + n_off + ni * 8 + (lane & 3) * 2;
            const float2 bs = *(const float2*)&bias[col];
#pragma unroll
            for (int h2 = 0; h2 < 2; h2++) {
                const int row = bm + m_off + mi * 16 + (lane >> 2) + h2 * 8;
                float2 v;
                v.x = acc[mi][ni][h2 * 2 + 0] + bs.x;
                v.y = acc[mi][ni][h2 * 2 + 1] + bs.y;
                if (headsplit) {
                    const int b_ = row >> 10, s_ = row & 1023;
                    const int h_ = col >> 6,  d_ = col & 63;
                    *(float2*)&dst[((size_t)(b_ * NH + h_) * S + s_) * HD + d_] = v;
                } else {
                    *(float2*)&dst[(size_t)row * H + col] = v;
                }
            }
        }
    }
}

// ---------------------------------------------------------------------------
// Scores: Sc = (Q @ K^T) * SCALE + mask  per head (K=64). Same MMA core.
// ---------------------------------------------------------------------------
__global__ __launch_bounds__(256, 1)
void attn_scores_mma(const float* __restrict__ mask)
{
    __shared__ __align__(16) uint16_t sAhi[128][40];
    __shared__ __align__(16) uint16_t sAlo[128][40];
    __shared__ __align__(16) uint16_t sBhi[128][40];
    __shared__ __align__(16) uint16_t sBlo[128][40];

    const int head = blockIdx.z;
    const int b_   = head >> 4;
    const float* Q = g_q + (size_t)head * S * HD;
    const float* K = g_k + (size_t)head * S * HD;
    float* Sc      = g_scores + (size_t)head * S * S;

    const int tid  = threadIdx.x;
    const int lane = tid & 31;
    const int wid  = tid >> 5;
    const int bm   = blockIdx.y * 128;
    const int bn   = blockIdx.x * 128;
    const int m_off = (wid & 1) * 64;
    const int n_off = (wid >> 1) * 32;

    const int lr = tid >> 1;
    const int lk = (tid & 1) * 16;
    const float* xrow = Q + (size_t)(bm + lr) * HD + lk;
    const float* wrow = K + (size_t)(bn + lr) * HD + lk;

    float4 bufA[4], bufB[4];
#pragma unroll
    for (int q = 0; q < 4; q++) {
        bufA[q] = *(const float4*)(xrow + q * 4);
        bufB[q] = *(const float4*)(wrow + q * 4);
    }

    float acc[4][4][4];
#pragma unroll
    for (int i = 0; i < 4; i++)
#pragma unroll
        for (int j = 0; j < 4; j++)
#pragma unroll
            for (int t = 0; t < 4; t++) acc[i][j][t] = 0.f;

    const int NS = HD / BK;  // 2 slabs
#pragma unroll
    for (int s = 0; s < NS; s++) {
#pragma unroll
        for (int q = 0; q < 4; q++) {
            sts_f4(&sAhi[lr][0], &sAlo[lr][0], lk + q * 4, bufA[q]);
            sts_f4(&sBhi[lr][0], &sBlo[lr][0], lk + q * 4, bufB[q]);
        }
        __syncthreads();
        if (s + 1 < NS) {
            const float* xp = xrow + (size_t)(s + 1) * BK;
            const float* wp = wrow + (size_t)(s + 1) * BK;
#pragma unroll
            for (int q = 0; q < 4; q++) {
                bufA[q] = *(const float4*)(xp + q * 4);
                bufB[q] = *(const float4*)(wp + q * 4);
            }
        }
#pragma unroll
        for (int kk = 0; kk < 2; kk++) {
            const int kel = kk * 16;
            uint32_t ah[4][4], al[4][4], bh[4][2], bl[4][2];
            const int ar = m_off + (lane & 15);
            const int ac = kel + (lane >> 4) * 8;
#pragma unroll
            for (int mi = 0; mi < 4; mi++) {
                ldm_x4(ah[mi], smem_u32(&sAhi[ar + mi * 16][ac]));
                ldm_x4(al[mi], smem_u32(&sAlo[ar + mi * 16][ac]));
            }
            const int br = n_off + (lane & 7);
            const int bc = kel + ((lane >> 3) & 1) * 8;
#pragma unroll
            for (int ni = 0; ni < 4; ni++) {
                ldm_x2(bh[ni], smem_u32(&sBhi[br + ni * 8][bc]));
                ldm_x2(bl[ni], smem_u32(&sBlo[br + ni * 8][bc]));
            }
#pragma unroll
            for (int mi = 0; mi < 4; mi++)
#pragma unroll
                for (int ni = 0; ni < 4; ni++) {
                    mma_bf16(acc[mi][ni], ah[mi], bh[ni]);
                    mma_bf16(acc[mi][ni], ah[mi], bl[ni]);
                    mma_bf16(acc[mi][ni], al[mi], bh[ni]);
                }
        }
        __syncthreads();
    }

#pragma unroll
    for (int mi = 0; mi < 4; mi++) {
#pragma unroll
        for (int ni = 0; ni < 4; ni++) {
            const int col = bn + n_off + ni * 8 + (lane & 3) * 2;
            const float2 mk = *(const float2*)&mask[b_ * S + col];
#pragma unroll
            for (int h2 = 0; h2 < 2; h2++) {
                const int row = bm + m_off + mi * 16 + (lane >> 2) + h2 * 8;
                float2 v;
                v.x = acc[mi][ni][h2 * 2 + 0] * SCALE + mk.x;
                v.y = acc[mi][ni][h2 * 2 + 1] * SCALE + mk.y;
                *(float2*)&Sc[(size_t)row * S + col] = v;
            }
        }
    }
}

// ---------------------------------------------------------------------------
// Row softmax over g_scores, in place.
// ---------------------------------------------------------------------------
__global__ __launch_bounds__(256, 1)
void softmax_rows()
{
    float* row = g_scores + (size_t)blockIdx.x * S;
    const int tid = threadIdx.x;
    __shared__ float red[8];

    float4 v = *(const float4*)&row[tid * 4];
    float m = fmaxf(fmaxf(v.x, v.y), fmaxf(v.z, v.w));
#pragma unroll
    for (int o = 16; o; o >>= 1) m = fmaxf(m, __shfl_xor_sync(~0u, m, o));
    if ((tid & 31) == 0) red[tid >> 5] = m;
    __syncthreads();
    float mm = -3.4e38f;
#pragma unroll
    for (int i = 0; i < 8; i++) mm = fmaxf(mm, red[i]);

    v.x = __expf(v.x - mm); v.y = __expf(v.y - mm);
    v.z = __expf(v.z - mm); v.w = __expf(v.w - mm);
    float s = v.x + v.y + v.z + v.w;
#pragma unroll
    for (int o = 16; o; o >>= 1) s += __shfl_xor_sync(~0u, s, o);
    __syncthreads();
    if ((tid & 31) == 0) red[tid >> 5] = s;
    __syncthreads();
    float tot = 0.f;
#pragma unroll
    for (int i = 0; i < 8; i++) tot += red[i];

    const float inv = 1.f / tot;
    v.x *= inv; v.y *= inv; v.z *= inv; v.w *= inv;
    *(float4*)&row[tid * 4] = v;
}

// ---------------------------------------------------------------------------
// ctx = P @ V per head. 128x64 tile, 8 warps (32x32). V via ldmatrix.trans.
// ---------------------------------------------------------------------------
__global__ __launch_bounds__(256, 1)
void attn_ctx_mma()
{
    __shared__ __align__(16) uint16_t sAhi[128][40];
    __shared__ __align__(16) uint16_t sAlo[128][40];
    __shared__ __align__(16) uint16_t sVhi[32][72];
    __shared__ __align__(16) uint16_t sVlo[32][72];

    const int head = blockIdx.y;
    const int b_   = head >> 4;
    const int h_   = head & 15;
    const float* P = g_scores + (size_t)head * S * S;
    const float* V = g_v + (size_t)head * S * HD;

    const int tid  = threadIdx.x;
    const int lane = tid & 31;
    const int wid  = tid >> 5;
    const int bm   = blockIdx.x * 128;
    const int m_off = (wid & 3) * 32;
    const int n_off = (wid >> 2) * 32;

    const int lr = tid >> 1;
    const int lk = (tid & 1) * 16;
    const float* arow = P + (size_t)(bm + lr) * S + lk;
    const int vr = tid >> 3;          // 0..31
    const int vc = (tid & 7) * 8;     // 0..56

    float4 bufA[4], bufV[2];
#pragma unroll
    for (int q = 0; q < 4; q++) bufA[q] = *(const float4*)(arow + q * 4);
    bufV[0] = *(const float4*)&V[(size_t)vr * HD + vc];
    bufV[1] = *(const float4*)&V[(size_t)vr * HD + vc + 4];

    float acc[2][4][4];
#pragma unroll
    for (int i = 0; i < 2; i++)
#pragma unroll
        for (int j = 0; j < 4; j++)
#pragma unroll
            for (int t = 0; t < 4; t++) acc[i][j][t] = 0.f;

    const int NS = S / BK;  // 32 slabs
    for (int s = 0; s < NS; s++) {
#pragma unroll
        for (int q = 0; q < 4; q++)
            sts_f4(&sAhi[lr][0], &sAlo[lr][0], lk + q * 4, bufA[q]);
        sts_f4(&sVhi[vr][0], &sVlo[vr][0], vc,     bufV[0]);
        sts_f4(&sVhi[vr][0], &sVlo[vr][0], vc + 4, bufV[1]);
        __syncthreads();
        if (s + 1 < NS) {
            const float* ap = arow + (size_t)(s + 1) * BK;
#pragma unroll
            for (int q = 0; q < 4; q++) bufA[q] = *(const float4*)(ap + q * 4);
            const float* vp = V + (size_t)((s + 1) * BK + vr) * HD + vc;
            bufV[0] = *(const float4*)(vp);
            bufV[1] = *(const float4*)(vp + 4);
        }
#pragma unroll
        for (int kk = 0; kk < 2; kk++) {
            const int kel = kk * 16;
            uint32_t ah[2][4], al[2][4], bh[4][2], bl[4][2];
            const int ar = m_off + (lane & 15);
            const int ac = kel + (lane >> 4) * 8;
#pragma unroll
            for (int mi = 0; mi < 2; mi++) {
                ldm_x4(ah[mi], smem_u32(&sAhi[ar + mi * 16][ac]));
                ldm_x4(al[mi], smem_u32(&sAlo[ar + mi * 16][ac]));
            }
            const int vrr = kel + (lane & 7) + ((lane >> 3) & 1) * 8;
#pragma unroll
            for (int ni = 0; ni < 4; ni++) {
                ldm_x2t(bh[ni], smem_u32(&sVhi[vrr][n_off + ni * 8]));
                ldm_x2t(bl[ni], smem_u32(&sVlo[vrr][n_off + ni * 8]));
            }
#pragma unroll
            for (int mi = 0; mi < 2; mi++)
#pragma unroll
                for (int ni = 0; ni < 4; ni++) {
                    mma_bf16(acc[mi][ni], ah[mi], bh[ni]);
                    mma_bf16(acc[mi][ni], ah[mi], bl[ni]);
                    mma_bf16(acc[mi][ni], al[mi], bh[ni]);
                }
        }
        __syncthreads();
    }

#pragma unroll
    for (int mi = 0; mi < 2; mi++) {
#pragma unroll
        for (int ni = 0; ni < 4; ni++) {
            const int d = n_off + ni * 8 + (lane & 3) * 2;
#pragma unroll
            for (int h2 = 0; h2 < 2; h2++) {
                const int q = bm + m_off + mi * 16 + (lane >> 2) + h2 * 8;
                float2 v;
                v.x = acc[mi][ni][h2 * 2 + 0];
                v.y = acc[mi][ni][h2 * 2 + 1];
                *(float2*)&g_ctx[((size_t)(b_ * S + q)) * H + h_ * HD + d] = v;
            }
        }
    }
}

// ---------------------------------------------------------------------------
// out = LayerNorm(g_proj + hidden) * gamma + beta
// ---------------------------------------------------------------------------
__global__ __launch_bounds__(256, 1)
void add_ln(const float* __restrict__ hidden,
            const float* __restrict__ gamma,
            const float* __restrict__ beta,
            float* __restrict__ out)
{
    const size_t row = blockIdx.x;
    const int tid = threadIdx.x;
    __shared__ float r1[8], r2[8];

    float4 a  = *(const float4*)&g_proj[row * H + tid * 4];
    float4 hv = *(const float4*)&hidden[row * H + tid * 4];
    float x0 = a.x + hv.x, x1 = a.y + hv.y, x2 = a.z + hv.z, x3 = a.w + hv.w;

    float s1 = x0 + x1 + x2 + x3;
    float s2 = fmaf(x0, x0, fmaf(x1, x1, fmaf(x2, x2, x3 * x3)));
#pragma unroll
    for (int o = 16; o; o >>= 1) {
        s1 += __shfl_xor_sync(~0u, s1, o);
        s2 += __shfl_xor_sync(~0u, s2, o);
    }
    if ((tid & 31) == 0) { r1[tid >> 5] = s1; r2[tid >> 5] = s2; }
    __syncthreads();
    float t1 = 0.f, t2 = 0.f;
#pragma unroll
    for (int i = 0; i < 8; i++) { t1 += r1[i]; t2 += r2[i]; }

    const float mu  = t1 * (1.f / H);
    const float var = t2 * (1.f / H) - mu * mu;
    const float inv = rsqrtf(var + LN_EPS);

    float4 g  = *(const float4*)&gamma[tid * 4];
    float4 bt = *(const float4*)&beta[tid * 4];
    float4 o;
    o.x = (x0 - mu) * inv * g.x + bt.x;
    o.y = (x1 - mu) * inv * g.y + bt.y;
    o.z = (x2 - mu) * inv * g.z + bt.z;
    o.w = (x3 - mu) * inv * g.w + bt.w;
    *(float4*)&out[row * H + tid * 4] = o;
}

// ---------------------------------------------------------------------------
extern "C" void kernel_launch(void* const* d_in, const int* in_sizes, int n_in,
                              void* d_out, int out_size)
{
    const float* hidden = (const float*)d_in[0];
    const float* mask   = (const float*)d_in[1];
    const float* Wq     = (const float*)d_in[2];
    const float* bq     = (const float*)d_in[3];
    const float* Wk     = (const float*)d_in[4];
    const float* bk     = (const float*)d_in[5];
    const float* Wv     = (const float*)d_in[6];
    const float* bv     = (const float*)d_in[7];
    const float* Wo     = (const float*)d_in[8];
    const float* bo     = (const float*)d_in[9];
    const float* gamma  = (const float*)d_in[10];
    const float* beta   = (const float*)d_in[11];
    float* out          = (float*)d_out;

    dim3 blk(256);
    dim3 gqkv(H / 128, M / 128);        // (8, 64)
    gemm_mma<<<gqkv, blk>>>(hidden, Wq, bq, 0);
    gemm_mma<<<gqkv, blk>>>(hidden, Wk, bk, 1);
    gemm_mma<<<gqkv, blk>>>(hidden, Wv, bv, 2);

    dim3 gsc(S / 128, S / 128, BH);     // (8, 8, 128)
    attn_scores_mma<<<gsc, blk>>>(mask);

    softmax_rows<<<BH * S, blk>>>();

    dim3 gctx(S / 128, BH);             // (8, 128)
    attn_ctx_mma<<<gctx, blk>>>();

    gemm_mma<<<gqkv, blk>>>(nullptr, Wo, bo, 3);

    add_ln<<<M, blk>>>(hidden, gamma, beta, out);
}

// round 4
// speedup vs baseline: 2.9856x; 1.2374x over previous
#include <cuda_runtime.h>
#include <cuda_bf16.h>
#include <cstdint>

namespace {
constexpr int B  = 8;
constexpr int S  = 1024;
constexpr int H  = 1024;
constexpr int NH = 16;
constexpr int HD = 64;
constexpr int M  = B * S;    // 8192 rows
constexpr int BH = B * NH;   // 128 heads
constexpr float SCALE  = 0.125f;
constexpr float LN_EPS = 1e-12f;
constexpr int BK = 32;       // K-slab per stage (projection GEMM)

// flash smem layout (uint16 elements, row stride 72)
constexpr int FQ_HI = 0;
constexpr int FQ_LO = 128 * 72;
constexpr int FK_HI = 2 * 128 * 72;
constexpr int FK_LO = 3 * 128 * 72;
constexpr int FV_HI = 4 * 128 * 72;
constexpr int FV_LO = 5 * 128 * 72;
constexpr int FLASH_U16  = 6 * 128 * 72;          // 55296 u16 = 110592 B
constexpr int FLASH_SMEM = FLASH_U16 * 2 + 512;   // + mask tile = 111104 B
}

// ---------------------------------------------------------------------------
// Scratch (allocation-free: __device__ globals)
// ---------------------------------------------------------------------------
__device__ float g_q[BH * S * HD];
__device__ float g_k[BH * S * HD];
__device__ float g_v[BH * S * HD];
__device__ float g_ctx[M * H];
__device__ float g_proj[M * H];

// ---------------------------------------------------------------------------
// Warp-MMA helpers
// ---------------------------------------------------------------------------
__device__ __forceinline__ uint32_t smem_u32(const void* p) {
    uint32_t a;
    asm("{ .reg .u64 t; cvta.to.shared.u64 t, %1; cvt.u32.u64 %0, t; }"
        : "=r"(a) : "l"(p));
    return a;
}
__device__ __forceinline__ void mma_bf16(float* c, const uint32_t* a, const uint32_t* b) {
    asm volatile(
        "mma.sync.aligned.m16n8k16.row.col.f32.bf16.bf16.f32 "
        "{%0,%1,%2,%3}, {%4,%5,%6,%7}, {%8,%9}, {%0,%1,%2,%3};"
        : "+f"(c[0]), "+f"(c[1]), "+f"(c[2]), "+f"(c[3])
        : "r"(a[0]), "r"(a[1]), "r"(a[2]), "r"(a[3]), "r"(b[0]), "r"(b[1]));
}
__device__ __forceinline__ void ldm_x4(uint32_t* r, uint32_t addr) {
    asm volatile("ldmatrix.sync.aligned.m8n8.x4.shared.b16 {%0,%1,%2,%3}, [%4];"
                 : "=r"(r[0]), "=r"(r[1]), "=r"(r[2]), "=r"(r[3]) : "r"(addr));
}
__device__ __forceinline__ void ldm_x2(uint32_t* r, uint32_t addr) {
    asm volatile("ldmatrix.sync.aligned.m8n8.x2.shared.b16 {%0,%1}, [%2];"
                 : "=r"(r[0]), "=r"(r[1]) : "r"(addr));
}
__device__ __forceinline__ void ldm_x2t(uint32_t* r, uint32_t addr) {
    asm volatile("ldmatrix.sync.aligned.m8n8.x2.trans.shared.b16 {%0,%1}, [%2];"
                 : "=r"(r[0]), "=r"(r[1]) : "r"(addr));
}
// Split (x,y) into packed bf16x2 hi (lo16=x) and residual lo.
__device__ __forceinline__ void split2(float x, float y, uint32_t& hi, uint32_t& lo) {
    asm("cvt.rn.bf16x2.f32 %0, %1, %2;" : "=r"(hi) : "f"(y), "f"(x));
    float hx = __uint_as_float(hi << 16);
    float hy = __uint_as_float(hi & 0xFFFF0000u);
    float rx = x - hx;
    float ry = y - hy;
    asm("cvt.rn.bf16x2.f32 %0, %1, %2;" : "=r"(lo) : "f"(ry), "f"(rx));
}
__device__ __forceinline__ void sts_f4(uint16_t* hiA, uint16_t* loA, int idx, float4 f) {
    uint32_t h0, l0, h1, l1;
    split2(f.x, f.y, h0, l0);
    split2(f.z, f.w, h1, l1);
    *(uint32_t*)&hiA[idx]     = h0;
    *(uint32_t*)&hiA[idx + 2] = h1;
    *(uint32_t*)&loA[idx]     = l0;
    *(uint32_t*)&loA[idx + 2] = l1;
}

// ---------------------------------------------------------------------------
// Projection GEMM: C[M,1024] = X @ W^T + bias.  128x128 tile, 8 warps (64x32).
// dst_sel: 0/1/2 -> q/k/v headsplit layout; 3 -> g_proj (X := g_ctx)
// ---------------------------------------------------------------------------
__global__ __launch_bounds__(256, 1)
void gemm_mma(const float* __restrict__ Xin,
              const float* __restrict__ W,
              const float* __restrict__ bias,
              int dst_sel)
{
    __shared__ __align__(16) uint16_t sAhi[128][40];
    __shared__ __align__(16) uint16_t sAlo[128][40];
    __shared__ __align__(16) uint16_t sBhi[128][40];
    __shared__ __align__(16) uint16_t sBlo[128][40];

    const float* X = Xin ? Xin : g_ctx;
    float* dst = (dst_sel == 0) ? g_q : (dst_sel == 1) ? g_k
               : (dst_sel == 2) ? g_v : g_proj;
    const bool headsplit = dst_sel < 3;

    const int tid  = threadIdx.x;
    const int lane = tid & 31;
    const int wid  = tid >> 5;
    const int bm   = blockIdx.y * 128;
    const int bn   = blockIdx.x * 128;
    const int m_off = (wid & 1) * 64;
    const int n_off = (wid >> 1) * 32;

    const int lr = tid >> 1;
    const int lk = (tid & 1) * 16;
    const float* xrow = X + (size_t)(bm + lr) * H + lk;
    const float* wrow = W + (size_t)(bn + lr) * H + lk;

    float4 bufA[4], bufB[4];
#pragma unroll
    for (int q = 0; q < 4; q++) {
        bufA[q] = *(const float4*)(xrow + q * 4);
        bufB[q] = *(const float4*)(wrow + q * 4);
    }

    float acc[4][4][4];
#pragma unroll
    for (int i = 0; i < 4; i++)
#pragma unroll
        for (int j = 0; j < 4; j++)
#pragma unroll
            for (int t = 0; t < 4; t++) acc[i][j][t] = 0.f;

    const int NS = H / BK;
    for (int s = 0; s < NS; s++) {
#pragma unroll
        for (int q = 0; q < 4; q++) {
            sts_f4(&sAhi[lr][0], &sAlo[lr][0], lk + q * 4, bufA[q]);
            sts_f4(&sBhi[lr][0], &sBlo[lr][0], lk + q * 4, bufB[q]);
        }
        __syncthreads();
        if (s + 1 < NS) {
            const float* xp = xrow + (size_t)(s + 1) * BK;
            const float* wp = wrow + (size_t)(s + 1) * BK;
#pragma unroll
            for (int q = 0; q < 4; q++) {
                bufA[q] = *(const float4*)(xp + q * 4);
                bufB[q] = *(const float4*)(wp + q * 4);
            }
        }
#pragma unroll
        for (int kk = 0; kk < 2; kk++) {
            const int kel = kk * 16;
            uint32_t ah[4][4], al[4][4], bh[4][2], bl[4][2];
            const int ar = m_off + (lane & 15);
            const int ac = kel + (lane >> 4) * 8;
#pragma unroll
            for (int mi = 0; mi < 4; mi++) {
                ldm_x4(ah[mi], smem_u32(&sAhi[ar + mi * 16][ac]));
                ldm_x4(al[mi], smem_u32(&sAlo[ar + mi * 16][ac]));
            }
            const int br = n_off + (lane & 7);
            const int bc = kel + ((lane >> 3) & 1) * 8;
#pragma unroll
            for (int ni = 0; ni < 4; ni++) {
                ldm_x2(bh[ni], smem_u32(&sBhi[br + ni * 8][bc]));
                ldm_x2(bl[ni], smem_u32(&sBlo[br + ni * 8][bc]));
            }
#pragma unroll
            for (int mi = 0; mi < 4; mi++)
#pragma unroll
                for (int ni = 0; ni < 4; ni++) {
                    mma_bf16(acc[mi][ni], ah[mi], bh[ni]);
                    mma_bf16(acc[mi][ni], ah[mi], bl[ni]);
                    mma_bf16(acc[mi][ni], al[mi], bh[ni]);
                }
        }
        __syncthreads();
    }

#pragma unroll
    for (int mi = 0; mi < 4; mi++) {
#pragma unroll
        for (int ni = 0; ni < 4; ni++) {
            const int col = bn + n_off + ni * 8 + (lane & 3) * 2;
            const float2 bs = *(const float2*)&bias[col];
#pragma unroll
            for (int h2 = 0; h2 < 2; h2++) {
                const int row = bm + m_off + mi * 16 + (lane >> 2) + h2 * 8;
                float2 v;
                v.x = acc[mi][ni][h2 * 2 + 0] + bs.x;
                v.y = acc[mi][ni][h2 * 2 + 1] + bs.y;
                if (headsplit) {
                    const int b_ = row >> 10, s_ = row & 1023;
                    const int h_ = col >> 6,  d_ = col & 63;
                    *(float2*)&dst[((size_t)(b_ * NH + h_) * S + s_) * HD + d_] = v;
                } else {
                    *(float2*)&dst[(size_t)row * H + col] = v;
                }
            }
        }
    }
}

// ---------------------------------------------------------------------------
// Flash attention: per block = (q-tile 128, head). QK^T -> online softmax -> PV.
// 8 warps x 16 q-rows. K/V tiles of 128 keys streamed through smem.
// ---------------------------------------------------------------------------
__global__ __launch_bounds__(256, 1)
void flash_attn(const float* __restrict__ mask)
{
    extern __shared__ __align__(16) char fsm[];
    uint16_t* sQhi = (uint16_t*)fsm + FQ_HI;
    uint16_t* sQlo = (uint16_t*)fsm + FQ_LO;
    uint16_t* sKhi = (uint16_t*)fsm + FK_HI;
    uint16_t* sKlo = (uint16_t*)fsm + FK_LO;
    uint16_t* sVhi = (uint16_t*)fsm + FV_HI;
    uint16_t* sVlo = (uint16_t*)fsm + FV_LO;
    float*    maskS = (float*)(fsm + FLASH_U16 * 2);

    const int head = blockIdx.y;
    const int b_   = head >> 4;
    const int h_   = head & 15;
    const float* Qg = g_q + (size_t)head * S * HD;
    const float* Kg = g_k + (size_t)head * S * HD;
    const float* Vg = g_v + (size_t)head * S * HD;
    const float* mrow = mask + (size_t)b_ * S;

    const int tid  = threadIdx.x;
    const int lane = tid & 31;
    const int w    = tid >> 5;
    const int bq   = blockIdx.x * 128;

    const int lr = tid >> 1;          // load row 0..127
    const int lk = (tid & 1) * 32;    // 32 floats per thread-half

    // ---- load Q tile, hoist A-fragments ----
    {
        const float* qp = Qg + (size_t)(bq + lr) * HD + lk;
#pragma unroll
        for (int q = 0; q < 8; q++)
            sts_f4(&sQhi[lr * 72], &sQlo[lr * 72], lk + q * 4,
                   *(const float4*)(qp + q * 4));
    }
    __syncthreads();

    uint32_t qh[4][4], ql[4][4];
    {
        const int ar = w * 16 + (lane & 15);
        const int acb = (lane >> 4) * 8;
#pragma unroll
        for (int kk = 0; kk < 4; kk++) {
            ldm_x4(qh[kk], smem_u32(&sQhi[ar * 72 + kk * 16 + acb]));
            ldm_x4(ql[kk], smem_u32(&sQlo[ar * 72 + kk * 16 + acb]));
        }
    }

    float acco[8][4];
#pragma unroll
    for (int i = 0; i < 8; i++)
#pragma unroll
        for (int t = 0; t < 4; t++) acco[i][t] = 0.f;
    float m0 = -3.4e38f, m1 = -3.4e38f, l0 = 0.f, l1 = 0.f;

    for (int j = 0; j < S / 128; j++) {
        __syncthreads();  // previous tile's smem reads done
        {
            const float* kp = Kg + (size_t)(j * 128 + lr) * HD + lk;
            const float* vp = Vg + (size_t)(j * 128 + lr) * HD + lk;
#pragma unroll
            for (int q = 0; q < 8; q++) {
                sts_f4(&sKhi[lr * 72], &sKlo[lr * 72], lk + q * 4,
                       *(const float4*)(kp + q * 4));
                sts_f4(&sVhi[lr * 72], &sVlo[lr * 72], lk + q * 4,
                       *(const float4*)(vp + q * 4));
            }
            if (tid < 128) maskS[tid] = mrow[j * 128 + tid];
        }
        __syncthreads();

        // ---- S = Q K^T ----
        float accs[16][4];
#pragma unroll
        for (int i = 0; i < 16; i++)
#pragma unroll
            for (int t = 0; t < 4; t++) accs[i][t] = 0.f;

#pragma unroll
        for (int kk = 0; kk < 4; kk++) {
            const int kcol = kk * 16 + ((lane >> 3) & 1) * 8;
            const int krb  = (lane & 7);
#pragma unroll
            for (int ni = 0; ni < 16; ni++) {
                uint32_t kh2[2], kl2[2];
                ldm_x2(kh2, smem_u32(&sKhi[(ni * 8 + krb) * 72 + kcol]));
                ldm_x2(kl2, smem_u32(&sKlo[(ni * 8 + krb) * 72 + kcol]));
                mma_bf16(accs[ni], qh[kk], kh2);
                mma_bf16(accs[ni], qh[kk], kl2);
                mma_bf16(accs[ni], ql[kk], kh2);
            }
        }

        // ---- scale + mask + online softmax ----
        float tmax0 = -3.4e38f, tmax1 = -3.4e38f;
#pragma unroll
        for (int ni = 0; ni < 16; ni++) {
            const int c = ni * 8 + (lane & 3) * 2;
            const float mk0 = maskS[c], mk1 = maskS[c + 1];
            accs[ni][0] = fmaf(accs[ni][0], SCALE, mk0);
            accs[ni][1] = fmaf(accs[ni][1], SCALE, mk1);
            accs[ni][2] = fmaf(accs[ni][2], SCALE, mk0);
            accs[ni][3] = fmaf(accs[ni][3], SCALE, mk1);
            tmax0 = fmaxf(tmax0, fmaxf(accs[ni][0], accs[ni][1]));
            tmax1 = fmaxf(tmax1, fmaxf(accs[ni][2], accs[ni][3]));
        }
        tmax0 = fmaxf(tmax0, __shfl_xor_sync(~0u, tmax0, 1));
        tmax0 = fmaxf(tmax0, __shfl_xor_sync(~0u, tmax0, 2));
        tmax1 = fmaxf(tmax1, __shfl_xor_sync(~0u, tmax1, 1));
        tmax1 = fmaxf(tmax1, __shfl_xor_sync(~0u, tmax1, 2));

        const float mn0 = fmaxf(m0, tmax0);
        const float mn1 = fmaxf(m1, tmax1);
        const float alpha0 = __expf(m0 - mn0);
        const float alpha1 = __expf(m1 - mn1);
        m0 = mn0; m1 = mn1;

        float sum0 = 0.f, sum1 = 0.f;
#pragma unroll
        for (int ni = 0; ni < 16; ni++) {
            accs[ni][0] = __expf(accs[ni][0] - mn0);
            accs[ni][1] = __expf(accs[ni][1] - mn0);
            accs[ni][2] = __expf(accs[ni][2] - mn1);
            accs[ni][3] = __expf(accs[ni][3] - mn1);
            sum0 += accs[ni][0] + accs[ni][1];
            sum1 += accs[ni][2] + accs[ni][3];
        }
        sum0 += __shfl_xor_sync(~0u, sum0, 1);
        sum0 += __shfl_xor_sync(~0u, sum0, 2);
        sum1 += __shfl_xor_sync(~0u, sum1, 1);
        sum1 += __shfl_xor_sync(~0u, sum1, 2);
        l0 = l0 * alpha0 + sum0;
        l1 = l1 * alpha1 + sum1;

#pragma unroll
        for (int ni = 0; ni < 8; ni++) {
            acco[ni][0] *= alpha0; acco[ni][1] *= alpha0;
            acco[ni][2] *= alpha1; acco[ni][3] *= alpha1;
        }

        // ---- O += P V  (P from registers: accum layout == A-frag layout) ----
#pragma unroll
        for (int kk = 0; kk < 8; kk++) {
            uint32_t ph[4], pl[4];
            split2(accs[2*kk][0],   accs[2*kk][1],   ph[0], pl[0]);
            split2(accs[2*kk][2],   accs[2*kk][3],   ph[1], pl[1]);
            split2(accs[2*kk+1][0], accs[2*kk+1][1], ph[2], pl[2]);
            split2(accs[2*kk+1][2], accs[2*kk+1][3], ph[3], pl[3]);
            const int vrow = kk * 16 + (lane & 7) + ((lane >> 3) & 1) * 8;
#pragma unroll
            for (int ni = 0; ni < 8; ni++) {
                uint32_t vh2[2], vl2[2];
                ldm_x2t(vh2, smem_u32(&sVhi[vrow * 72 + ni * 8]));
                ldm_x2t(vl2, smem_u32(&sVlo[vrow * 72 + ni * 8]));
                mma_bf16(acco[ni], ph, vh2);
                mma_bf16(acco[ni], ph, vl2);
                mma_bf16(acco[ni], pl, vh2);
            }
        }
    }

    // ---- finalize: divide by l, write ctx [B,S,H] ----
    const float inv0 = 1.f / l0;
    const float inv1 = 1.f / l1;
    const int q0 = bq + w * 16 + (lane >> 2);
#pragma unroll
    for (int ni = 0; ni < 8; ni++) {
        const int d = ni * 8 + (lane & 3) * 2;
        float2 v0; v0.x = acco[ni][0] * inv0; v0.y = acco[ni][1] * inv0;
        float2 v1; v1.x = acco[ni][2] * inv1; v1.y = acco[ni][3] * inv1;
        *(float2*)&g_ctx[((size_t)(b_ * S + q0)) * H + h_ * HD + d] = v0;
        *(float2*)&g_ctx[((size_t)(b_ * S + q0 + 8)) * H + h_ * HD + d] = v1;
    }
}

// ---------------------------------------------------------------------------
// out = LayerNorm(g_proj + hidden) * gamma + beta
// ---------------------------------------------------------------------------
__global__ __launch_bounds__(256, 1)
void add_ln(const float* __restrict__ hidden,
            const float* __restrict__ gamma,
            const float* __restrict__ beta,
            float* __restrict__ out)
{
    const size_t row = blockIdx.x;
    const int tid = threadIdx.x;
    __shared__ float r1[8], r2[8];

    float4 a  = *(const float4*)&g_proj[row * H + tid * 4];
    float4 hv = *(const float4*)&hidden[row * H + tid * 4];
    float x0 = a.x + hv.x, x1 = a.y + hv.y, x2 = a.z + hv.z, x3 = a.w + hv.w;

    float s1 = x0 + x1 + x2 + x3;
    float s2 = fmaf(x0, x0, fmaf(x1, x1, fmaf(x2, x2, x3 * x3)));
#pragma unroll
    for (int o = 16; o; o >>= 1) {
        s1 += __shfl_xor_sync(~0u, s1, o);
        s2 += __shfl_xor_sync(~0u, s2, o);
    }
    if ((tid & 31) == 0) { r1[tid >> 5] = s1; r2[tid >> 5] = s2; }
    __syncthreads();
    float t1 = 0.f, t2 = 0.f;
#pragma unroll
    for (int i = 0; i < 8; i++) { t1 += r1[i]; t2 += r2[i]; }

    const float mu  = t1 * (1.f / H);
    const float var = t2 * (1.f / H) - mu * mu;
    const float inv = rsqrtf(var + LN_EPS);

    float4 g  = *(const float4*)&gamma[tid * 4];
    float4 bt = *(const float4*)&beta[tid * 4];
    float4 o;
    o.x = (x0 - mu) * inv * g.x + bt.x;
    o.y = (x1 - mu) * inv * g.y + bt.y;
    o.z = (x2 - mu) * inv * g.z + bt.z;
    o.w = (x3 - mu) * inv * g.w + bt.w;
    *(float4*)&out[row * H + tid * 4] = o;
}

// ---------------------------------------------------------------------------
extern "C" void kernel_launch(void* const* d_in, const int* in_sizes, int n_in,
                              void* d_out, int out_size)
{
    const float* hidden = (const float*)d_in[0];
    const float* mask   = (const float*)d_in[1];
    const float* Wq     = (const float*)d_in[2];
    const float* bq     = (const float*)d_in[3];
    const float* Wk     = (const float*)d_in[4];
    const float* bk     = (const float*)d_in[5];
    const float* Wv     = (const float*)d_in[6];
    const float* bv     = (const float*)d_in[7];
    const float* Wo     = (const float*)d_in[8];
    const float* bo     = (const float*)d_in[9];
    const float* gamma  = (const float*)d_in[10];
    const float* beta   = (const float*)d_in[11];
    float* out          = (float*)d_out;

    cudaFuncSetAttribute(flash_attn, cudaFuncAttributeMaxDynamicSharedMemorySize,
                         FLASH_SMEM);

    dim3 blk(256);
    dim3 gqkv(H / 128, M / 128);        // (8, 64)
    gemm_mma<<<gqkv, blk>>>(hidden, Wq, bq, 0);
    gemm_mma<<<gqkv, blk>>>(hidden, Wk, bk, 1);
    gemm_mma<<<gqkv, blk>>>(hidden, Wv, bv, 2);

    dim3 gfa(S / 128, BH);              // (8, 128)
    flash_attn<<<gfa, blk, FLASH_SMEM>>>(mask);

    gemm_mma<<<gqkv, blk>>>(nullptr, Wo, bo, 3);

    add_ln<<<M, blk>>>(hidden, gamma, beta, out);
}

// round 5
// speedup vs baseline: 3.2822x; 1.0994x over previous
#include <cuda_runtime.h>
#include <cuda_bf16.h>
#include <cstdint>

namespace {
constexpr int B  = 8;
constexpr int S  = 1024;
constexpr int H  = 1024;
constexpr int NH = 16;
constexpr int HD = 64;
constexpr int M  = B * S;    // 8192
constexpr int BH = B * NH;   // 128
constexpr float SCALE  = 0.125f;
constexpr float LN_EPS = 1e-12f;
constexpr int BK = 32;

// flash smem (u16 units, row stride 72)
constexpr int FQ_HI = 0;
constexpr int FQ_LO = 128 * 72;
constexpr int FK_HI = 2 * 128 * 72;
constexpr int FK_LO = 3 * 128 * 72;
constexpr int FV_HI = 4 * 128 * 72;
constexpr int FV_LO = 5 * 128 * 72;
constexpr int FLASH_U16  = 6 * 128 * 72;
constexpr int FLASH_SMEM = FLASH_U16 * 2 + 512;
}

// ---------------------------------------------------------------------------
// Scratch (allocation-free: __device__ globals)
// ---------------------------------------------------------------------------
__device__ __nv_bfloat16 g_hh[M * H],  g_hl[M * H];        // hidden hi/lo
__device__ __nv_bfloat16 g_wh[4u * H * H], g_wl[4u * H * H]; // Wq,Wk,Wv,Wo
__device__ __nv_bfloat16 g_qh[BH*S*HD], g_ql[BH*S*HD];
__device__ __nv_bfloat16 g_kh[BH*S*HD], g_kl[BH*S*HD];
__device__ __nv_bfloat16 g_vh[BH*S*HD], g_vl[BH*S*HD];
__device__ __nv_bfloat16 g_ch[M * H],  g_cl[M * H];        // ctx hi/lo
__device__ float g_proj[M * H];

// ---------------------------------------------------------------------------
// helpers
// ---------------------------------------------------------------------------
__device__ __forceinline__ uint32_t smem_u32(const void* p) {
    uint32_t a;
    asm("{ .reg .u64 t; cvta.to.shared.u64 t, %1; cvt.u32.u64 %0, t; }"
        : "=r"(a) : "l"(p));
    return a;
}
__device__ __forceinline__ void mma_bf16(float* c, const uint32_t* a, const uint32_t* b) {
    asm volatile(
        "mma.sync.aligned.m16n8k16.row.col.f32.bf16.bf16.f32 "
        "{%0,%1,%2,%3}, {%4,%5,%6,%7}, {%8,%9}, {%0,%1,%2,%3};"
        : "+f"(c[0]), "+f"(c[1]), "+f"(c[2]), "+f"(c[3])
        : "r"(a[0]), "r"(a[1]), "r"(a[2]), "r"(a[3]), "r"(b[0]), "r"(b[1]));
}
__device__ __forceinline__ void ldm_x4(uint32_t* r, uint32_t addr) {
    asm volatile("ldmatrix.sync.aligned.m8n8.x4.shared.b16 {%0,%1,%2,%3}, [%4];"
                 : "=r"(r[0]), "=r"(r[1]), "=r"(r[2]), "=r"(r[3]) : "r"(addr));
}
__device__ __forceinline__ void ldm_x4t(uint32_t* r, uint32_t addr) {
    asm volatile("ldmatrix.sync.aligned.m8n8.x4.trans.shared.b16 {%0,%1,%2,%3}, [%4];"
                 : "=r"(r[0]), "=r"(r[1]), "=r"(r[2]), "=r"(r[3]) : "r"(addr));
}
// Split (x,y) -> packed bf16x2 hi (lo16 = x) and residual lo.
__device__ __forceinline__ void split2(float x, float y, uint32_t& hi, uint32_t& lo) {
    asm("cvt.rn.bf16x2.f32 %0, %1, %2;" : "=r"(hi) : "f"(y), "f"(x));
    float hx = __uint_as_float(hi << 16);
    float hy = __uint_as_float(hi & 0xFFFF0000u);
    float rx = x - hx;
    float ry = y - hy;
    asm("cvt.rn.bf16x2.f32 %0, %1, %2;" : "=r"(lo) : "f"(ry), "f"(rx));
}
__device__ __forceinline__ void st_u16x16(uint16_t* p, uint4 a, uint4 b) {
    uint2* q = (uint2*)p;  // p is 8B-aligned (row stride 80B, lk*2 in {0,32})
    q[0] = make_uint2(a.x, a.y);
    q[1] = make_uint2(a.z, a.w);
    q[2] = make_uint2(b.x, b.y);
    q[3] = make_uint2(b.z, b.w);
}

// ---------------------------------------------------------------------------
// One-time fp32 -> hi/lo bf16 split. 4 elems/thread.
// sel: 0 -> hidden (g_hh/g_hl), 1..4 -> weight slot sel-1 (g_wh/g_wl).
// ---------------------------------------------------------------------------
__global__ __launch_bounds__(256, 8)
void cvt_split(const float* __restrict__ src, int sel)
{
    __nv_bfloat16* hi = (sel == 0) ? g_hh : g_wh + (size_t)(sel - 1) * H * H;
    __nv_bfloat16* lo = (sel == 0) ? g_hl : g_wl + (size_t)(sel - 1) * H * H;
    const size_t i = ((size_t)blockIdx.x * 256 + threadIdx.x) * 4;
    float4 f = *(const float4*)&src[i];
    uint32_t h0, l0, h1, l1;
    split2(f.x, f.y, h0, l0);
    split2(f.z, f.w, h1, l1);
    *(uint2*)&hi[i] = make_uint2(h0, h1);
    *(uint2*)&lo[i] = make_uint2(l0, l1);
}

// ---------------------------------------------------------------------------
// bf16 GEMM: C = X @ W^T + bias.  128x128 tile, 8 warps (64x32 each).
// X,W pre-split hi/lo bf16. 3-term MMA.
// dst_sel 0/1/2 -> q/k/v hi/lo headsplit; 3 -> g_proj fp32 (X := ctx hi/lo)
// ---------------------------------------------------------------------------
__global__ __launch_bounds__(256, 1)
void gemm_bf16(const float* __restrict__ bias, int dst_sel)
{
    __shared__ __align__(16) uint16_t sAhi[128][40];
    __shared__ __align__(16) uint16_t sAlo[128][40];
    __shared__ __align__(16) uint16_t sBhi[128][40];
    __shared__ __align__(16) uint16_t sBlo[128][40];

    const bool headsplit = dst_sel < 3;
    const __nv_bfloat16* Xhi = headsplit ? g_hh : g_ch;
    const __nv_bfloat16* Xlo = headsplit ? g_hl : g_cl;
    const __nv_bfloat16* Whi = g_wh + (size_t)dst_sel * H * H;
    const __nv_bfloat16* Wlo = g_wl + (size_t)dst_sel * H * H;
    __nv_bfloat16* dhi = (dst_sel == 0) ? g_qh : (dst_sel == 1) ? g_kh : g_vh;
    __nv_bfloat16* dlo = (dst_sel == 0) ? g_ql : (dst_sel == 1) ? g_kl : g_vl;

    const int tid  = threadIdx.x;
    const int lane = tid & 31;
    const int wid  = tid >> 5;
    const int bm   = blockIdx.y * 128;
    const int bn   = blockIdx.x * 128;
    const int m_off = (wid & 1) * 64;
    const int n_off = (wid >> 1) * 32;

    const int lr = tid >> 1;          // 0..127
    const int lk = (tid & 1) * 16;    // 16 halves per thread-half
    const uint4* xh = (const uint4*)(Xhi + (size_t)(bm + lr) * H) + (lk >> 3);
    const uint4* xl = (const uint4*)(Xlo + (size_t)(bm + lr) * H) + (lk >> 3);
    const uint4* wh = (const uint4*)(Whi + (size_t)(bn + lr) * H) + (lk >> 3);
    const uint4* wl = (const uint4*)(Wlo + (size_t)(bn + lr) * H) + (lk >> 3);

    uint4 bAh0 = xh[0], bAh1 = xh[1];
    uint4 bAl0 = xl[0], bAl1 = xl[1];
    uint4 bBh0 = wh[0], bBh1 = wh[1];
    uint4 bBl0 = wl[0], bBl1 = wl[1];

    float acc[4][4][4];
#pragma unroll
    for (int i = 0; i < 4; i++)
#pragma unroll
        for (int j = 0; j < 4; j++)
#pragma unroll
            for (int t = 0; t < 4; t++) acc[i][j][t] = 0.f;

    const int NS = H / BK;  // 32
    for (int s = 0; s < NS; s++) {
        st_u16x16(&sAhi[lr][lk], bAh0, bAh1);
        st_u16x16(&sAlo[lr][lk], bAl0, bAl1);
        st_u16x16(&sBhi[lr][lk], bBh0, bBh1);
        st_u16x16(&sBlo[lr][lk], bBl0, bBl1);
        __syncthreads();
        if (s + 1 < NS) {
            const int o = (s + 1) * 4;
            bAh0 = xh[o]; bAh1 = xh[o + 1];
            bAl0 = xl[o]; bAl1 = xl[o + 1];
            bBh0 = wh[o]; bBh1 = wh[o + 1];
            bBl0 = wl[o]; bBl1 = wl[o + 1];
        }
#pragma unroll
        for (int kk = 0; kk < 2; kk++) {
            const int kel = kk * 16;
            uint32_t ah[4][4], al[4][4], bh[2][4], bl[2][4];
            const int ar = m_off + (lane & 15);
            const int ac = kel + (lane >> 4) * 8;
#pragma unroll
            for (int mi = 0; mi < 4; mi++) {
                ldm_x4(ah[mi], smem_u32(&sAhi[ar + mi * 16][ac]));
                ldm_x4(al[mi], smem_u32(&sAlo[ar + mi * 16][ac]));
            }
            const int br = n_off + (lane & 7) + ((lane >> 4) & 1) * 8;
            const int bc = kel + ((lane >> 3) & 1) * 8;
#pragma unroll
            for (int np = 0; np < 2; np++) {
                ldm_x4(bh[np], smem_u32(&sBhi[br + np * 16][bc]));
                ldm_x4(bl[np], smem_u32(&sBlo[br + np * 16][bc]));
            }
#pragma unroll
            for (int mi = 0; mi < 4; mi++)
#pragma unroll
                for (int np = 0; np < 2; np++)
#pragma unroll
                    for (int half = 0; half < 2; half++) {
                        const int ni = np * 2 + half;
                        const uint32_t* bhp = &bh[np][half * 2];
                        const uint32_t* blp = &bl[np][half * 2];
                        mma_bf16(acc[mi][ni], ah[mi], bhp);
                        mma_bf16(acc[mi][ni], ah[mi], blp);
                        mma_bf16(acc[mi][ni], al[mi], bhp);
                    }
        }
        __syncthreads();
    }

#pragma unroll
    for (int mi = 0; mi < 4; mi++) {
#pragma unroll
        for (int ni = 0; ni < 4; ni++) {
            const int col = bn + n_off + ni * 8 + (lane & 3) * 2;
            const float2 bs = *(const float2*)&bias[col];
#pragma unroll
            for (int h2 = 0; h2 < 2; h2++) {
                const int row = bm + m_off + mi * 16 + (lane >> 2) + h2 * 8;
                float vx = acc[mi][ni][h2 * 2 + 0] + bs.x;
                float vy = acc[mi][ni][h2 * 2 + 1] + bs.y;
                if (headsplit) {
                    const int b_ = row >> 10, s_ = row & 1023;
                    const int h_ = col >> 6,  d_ = col & 63;
                    const size_t idx = ((size_t)(b_ * NH + h_) * S + s_) * HD + d_;
                    uint32_t hp, lp;
                    split2(vx, vy, hp, lp);
                    *(uint32_t*)&dhi[idx] = hp;
                    *(uint32_t*)&dlo[idx] = lp;
                } else {
                    float2 v; v.x = vx; v.y = vy;
                    *(float2*)&g_proj[(size_t)row * H + col] = v;
                }
            }
        }
    }
}

// ---------------------------------------------------------------------------
// Flash attention, bf16 hi/lo inputs. Block = (q-tile 128, head); 8 warps.
// ---------------------------------------------------------------------------
__global__ __launch_bounds__(256, 1)
void flash_attn(const float* __restrict__ mask)
{
    extern __shared__ __align__(16) char fsm[];
    uint16_t* sQhi = (uint16_t*)fsm + FQ_HI;
    uint16_t* sQlo = (uint16_t*)fsm + FQ_LO;
    uint16_t* sKhi = (uint16_t*)fsm + FK_HI;
    uint16_t* sKlo = (uint16_t*)fsm + FK_LO;
    uint16_t* sVhi = (uint16_t*)fsm + FV_HI;
    uint16_t* sVlo = (uint16_t*)fsm + FV_LO;
    float*    maskS = (float*)(fsm + FLASH_U16 * 2);

    const int head = blockIdx.y;
    const int b_   = head >> 4;
    const int h_   = head & 15;
    const size_t hbase = (size_t)head * S * HD;
    const float* mrow = mask + (size_t)b_ * S;

    const int tid  = threadIdx.x;
    const int lane = tid & 31;
    const int w    = tid >> 5;
    const int bq   = blockIdx.x * 128;

    const int lr = tid >> 1;          // 0..127
    const int lk = (tid & 1) * 32;    // 32 halves = 4 uint4

    // ---- Q tile -> smem, hoist fragments ----
    {
        const uint4* qh4 = (const uint4*)(g_qh + hbase + (size_t)(bq + lr) * HD + lk);
        const uint4* ql4 = (const uint4*)(g_ql + hbase + (size_t)(bq + lr) * HD + lk);
        uint4* dh = (uint4*)&sQhi[lr * 72 + lk];
        uint4* dl = (uint4*)&sQlo[lr * 72 + lk];
#pragma unroll
        for (int q = 0; q < 4; q++) { dh[q] = qh4[q]; dl[q] = ql4[q]; }
    }
    __syncthreads();

    uint32_t qh[4][4], ql[4][4];
    {
        const int ar = w * 16 + (lane & 15);
        const int acb = (lane >> 4) * 8;
#pragma unroll
        for (int kk = 0; kk < 4; kk++) {
            ldm_x4(qh[kk], smem_u32(&sQhi[ar * 72 + kk * 16 + acb]));
            ldm_x4(ql[kk], smem_u32(&sQlo[ar * 72 + kk * 16 + acb]));
        }
    }

    float acco[8][4];
#pragma unroll
    for (int i = 0; i < 8; i++)
#pragma unroll
        for (int t = 0; t < 4; t++) acco[i][t] = 0.f;
    float m0 = -3.4e38f, m1 = -3.4e38f, l0 = 0.f, l1 = 0.f;

    for (int j = 0; j < S / 128; j++) {
        __syncthreads();
        {
            const size_t off = hbase + (size_t)(j * 128 + lr) * HD + lk;
            const uint4* kh4 = (const uint4*)(g_kh + off);
            const uint4* kl4 = (const uint4*)(g_kl + off);
            const uint4* vh4 = (const uint4*)(g_vh + off);
            const uint4* vl4 = (const uint4*)(g_vl + off);
            uint4* dkh = (uint4*)&sKhi[lr * 72 + lk];
            uint4* dkl = (uint4*)&sKlo[lr * 72 + lk];
            uint4* dvh = (uint4*)&sVhi[lr * 72 + lk];
            uint4* dvl = (uint4*)&sVlo[lr * 72 + lk];
#pragma unroll
            for (int q = 0; q < 4; q++) {
                dkh[q] = kh4[q]; dkl[q] = kl4[q];
                dvh[q] = vh4[q]; dvl[q] = vl4[q];
            }
            if (tid < 128) maskS[tid] = mrow[j * 128 + tid];
        }
        __syncthreads();

        // ---- S = Q K^T (x4 K fragment loads: ni pairs) ----
        float accs[16][4];
#pragma unroll
        for (int i = 0; i < 16; i++)
#pragma unroll
            for (int t = 0; t < 4; t++) accs[i][t] = 0.f;

#pragma unroll
        for (int kk = 0; kk < 4; kk++) {
            const int krow = (lane & 7) + ((lane >> 4) & 1) * 8;
            const int kcol = kk * 16 + ((lane >> 3) & 1) * 8;
#pragma unroll
            for (int np = 0; np < 8; np++) {
                uint32_t kh4[4], kl4[4];
                ldm_x4(kh4, smem_u32(&sKhi[(np * 16 + krow) * 72 + kcol]));
                ldm_x4(kl4, smem_u32(&sKlo[(np * 16 + krow) * 72 + kcol]));
                mma_bf16(accs[2*np],   qh[kk], &kh4[0]);
                mma_bf16(accs[2*np],   qh[kk], &kl4[0]);
                mma_bf16(accs[2*np],   ql[kk], &kh4[0]);
                mma_bf16(accs[2*np+1], qh[kk], &kh4[2]);
                mma_bf16(accs[2*np+1], qh[kk], &kl4[2]);
                mma_bf16(accs[2*np+1], ql[kk], &kh4[2]);
            }
        }

        // ---- scale + mask + online softmax ----
        float tmax0 = -3.4e38f, tmax1 = -3.4e38f;
#pragma unroll
        for (int ni = 0; ni < 16; ni++) {
            const int c = ni * 8 + (lane & 3) * 2;
            const float mk0 = maskS[c], mk1 = maskS[c + 1];
            accs[ni][0] = fmaf(accs[ni][0], SCALE, mk0);
            accs[ni][1] = fmaf(accs[ni][1], SCALE, mk1);
            accs[ni][2] = fmaf(accs[ni][2], SCALE, mk0);
            accs[ni][3] = fmaf(accs[ni][3], SCALE, mk1);
            tmax0 = fmaxf(tmax0, fmaxf(accs[ni][0], accs[ni][1]));
            tmax1 = fmaxf(tmax1, fmaxf(accs[ni][2], accs[ni][3]));
        }
        tmax0 = fmaxf(tmax0, __shfl_xor_sync(~0u, tmax0, 1));
        tmax0 = fmaxf(tmax0, __shfl_xor_sync(~0u, tmax0, 2));
        tmax1 = fmaxf(tmax1, __shfl_xor_sync(~0u, tmax1, 1));
        tmax1 = fmaxf(tmax1, __shfl_xor_sync(~0u, tmax1, 2));

        const float mn0 = fmaxf(m0, tmax0);
        const float mn1 = fmaxf(m1, tmax1);
        const float alpha0 = __expf(m0 - mn0);
        const float alpha1 = __expf(m1 - mn1);
        m0 = mn0; m1 = mn1;

        float sum0 = 0.f, sum1 = 0.f;
#pragma unroll
        for (int ni = 0; ni < 16; ni++) {
            accs[ni][0] = __expf(accs[ni][0] - mn0);
            accs[ni][1] = __expf(accs[ni][1] - mn0);
            accs[ni][2] = __expf(accs[ni][2] - mn1);
            accs[ni][3] = __expf(accs[ni][3] - mn1);
            sum0 += accs[ni][0] + accs[ni][1];
            sum1 += accs[ni][2] + accs[ni][3];
        }
        sum0 += __shfl_xor_sync(~0u, sum0, 1);
        sum0 += __shfl_xor_sync(~0u, sum0, 2);
        sum1 += __shfl_xor_sync(~0u, sum1, 1);
        sum1 += __shfl_xor_sync(~0u, sum1, 2);
        l0 = l0 * alpha0 + sum0;
        l1 = l1 * alpha1 + sum1;

#pragma unroll
        for (int ni = 0; ni < 8; ni++) {
            acco[ni][0] *= alpha0; acco[ni][1] *= alpha0;
            acco[ni][2] *= alpha1; acco[ni][3] *= alpha1;
        }

        // ---- O += P V  (x4 trans V fragment loads: ni pairs) ----
#pragma unroll
        for (int kk = 0; kk < 8; kk++) {
            uint32_t ph[4], pl[4];
            split2(accs[2*kk][0],   accs[2*kk][1],   ph[0], pl[0]);
            split2(accs[2*kk][2],   accs[2*kk][3],   ph[1], pl[1]);
            split2(accs[2*kk+1][0], accs[2*kk+1][1], ph[2], pl[2]);
            split2(accs[2*kk+1][2], accs[2*kk+1][3], ph[3], pl[3]);
            const int vrow = kk * 16 + (lane & 7) + ((lane >> 3) & 1) * 8;
#pragma unroll
            for (int np = 0; np < 4; np++) {
                const int vcol = np * 16 + (lane >> 4) * 8;
                uint32_t vh4[4], vl4[4];
                ldm_x4t(vh4, smem_u32(&sVhi[vrow * 72 + vcol]));
                ldm_x4t(vl4, smem_u32(&sVlo[vrow * 72 + vcol]));
                mma_bf16(acco[2*np],   ph, &vh4[0]);
                mma_bf16(acco[2*np],   ph, &vl4[0]);
                mma_bf16(acco[2*np],   pl, &vh4[0]);
                mma_bf16(acco[2*np+1], ph, &vh4[2]);
                mma_bf16(acco[2*np+1], ph, &vl4[2]);
                mma_bf16(acco[2*np+1], pl, &vh4[2]);
            }
        }
    }

    // ---- finalize: /l, split, write ctx hi/lo [B,S,H] ----
    const float inv0 = 1.f / l0;
    const float inv1 = 1.f / l1;
    const int q0 = bq + w * 16 + (lane >> 2);
#pragma unroll
    for (int ni = 0; ni < 8; ni++) {
        const int d = ni * 8 + (lane & 3) * 2;
        const size_t i0 = ((size_t)(b_ * S + q0)) * H + h_ * HD + d;
        const size_t i1 = ((size_t)(b_ * S + q0 + 8)) * H + h_ * HD + d;
        uint32_t hp, lp;
        split2(acco[ni][0] * inv0, acco[ni][1] * inv0, hp, lp);
        *(uint32_t*)&g_ch[i0] = hp;
        *(uint32_t*)&g_cl[i0] = lp;
        split2(acco[ni][2] * inv1, acco[ni][3] * inv1, hp, lp);
        *(uint32_t*)&g_ch[i1] = hp;
        *(uint32_t*)&g_cl[i1] = lp;
    }
}

// ---------------------------------------------------------------------------
// out = LayerNorm(g_proj + hidden) * gamma + beta
// ---------------------------------------------------------------------------
__global__ __launch_bounds__(256, 1)
void add_ln(const float* __restrict__ hidden,
            const float* __restrict__ gamma,
            const float* __restrict__ beta,
            float* __restrict__ out)
{
    const size_t row = blockIdx.x;
    const int tid = threadIdx.x;
    __shared__ float r1[8], r2[8];

    float4 a  = *(const float4*)&g_proj[row * H + tid * 4];
    float4 hv = *(const float4*)&hidden[row * H + tid * 4];
    float x0 = a.x + hv.x, x1 = a.y + hv.y, x2 = a.z + hv.z, x3 = a.w + hv.w;

    float s1 = x0 + x1 + x2 + x3;
    float s2 = fmaf(x0, x0, fmaf(x1, x1, fmaf(x2, x2, x3 * x3)));
#pragma unroll
    for (int o = 16; o; o >>= 1) {
        s1 += __shfl_xor_sync(~0u, s1, o);
        s2 += __shfl_xor_sync(~0u, s2, o);
    }
    if ((tid & 31) == 0) { r1[tid >> 5] = s1; r2[tid >> 5] = s2; }
    __syncthreads();
    float t1 = 0.f, t2 = 0.f;
#pragma unroll
    for (int i = 0; i < 8; i++) { t1 += r1[i]; t2 += r2[i]; }

    const float mu  = t1 * (1.f / H);
    const float var = t2 * (1.f / H) - mu * mu;
    const float inv = rsqrtf(var + LN_EPS);

    float4 g  = *(const float4*)&gamma[tid * 4];
    float4 bt = *(const float4*)&beta[tid * 4];
    float4 o;
    o.x = (x0 - mu) * inv * g.x + bt.x;
    o.y = (x1 - mu) * inv * g.y + bt.y;
    o.z = (x2 - mu) * inv * g.z + bt.z;
    o.w = (x3 - mu) * inv * g.w + bt.w;
    *(float4*)&out[row * H + tid * 4] = o;
}

// ---------------------------------------------------------------------------
extern "C" void kernel_launch(void* const* d_in, const int* in_sizes, int n_in,
                              void* d_out, int out_size)
{
    const float* hidden = (const float*)d_in[0];
    const float* mask   = (const float*)d_in[1];
    const float* Wq     = (const float*)d_in[2];
    const float* bq     = (const float*)d_in[3];
    const float* Wk     = (const float*)d_in[4];
    const float* bk     = (const float*)d_in[5];
    const float* Wv     = (const float*)d_in[6];
    const float* bv     = (const float*)d_in[7];
    const float* Wo     = (const float*)d_in[8];
    const float* bo     = (const float*)d_in[9];
    const float* gamma  = (const float*)d_in[10];
    const float* beta   = (const float*)d_in[11];
    float* out          = (float*)d_out;

    cudaFuncSetAttribute(flash_attn, cudaFuncAttributeMaxDynamicSharedMemorySize,
                         FLASH_SMEM);

    dim3 blk(256);
    cvt_split<<<(M * H) / 1024, blk>>>(hidden, 0);
    cvt_split<<<(H * H) / 1024, blk>>>(Wq, 1);
    cvt_split<<<(H * H) / 1024, blk>>>(Wk, 2);
    cvt_split<<<(H * H) / 1024, blk>>>(Wv, 3);
    cvt_split<<<(H * H) / 1024, blk>>>(Wo, 4);

    dim3 gqkv(H / 128, M / 128);        // (8, 64)
    gemm_bf16<<<gqkv, blk>>>(bq, 0);
    gemm_bf16<<<gqkv, blk>>>(bk, 1);
    gemm_bf16<<<gqkv, blk>>>(bv, 2);

    dim3 gfa(S / 128, BH);              // (8, 128)
    flash_attn<<<gfa, blk, FLASH_SMEM>>>(mask);

    gemm_bf16<<<gqkv, blk>>>(bo, 3);

    add_ln<<<M, blk>>>(hidden, gamma, beta, out);
}